// round 8
// baseline (speedup 1.0000x reference)
#include <cuda_runtime.h>
#include <cuda_bf16.h>

#define NN 50000
#define EE 800000
#define LL 4

// ---------------- packed bf16 hi/lo storage ----------------
// node array [N][64] fp32 -> u32 words, interleaved: word 2j = (bf16 hi of col2j, col2j+1),
// word 2j+1 = (bf16 lo residuals). Row = 64 u32 = 256B.
__device__ unsigned g_h[NN * 64];
__device__ unsigned g_p[NN * 64];
__device__ unsigned g_EA[NN * 64];
__device__ unsigned g_EB[NN * 64];
__device__ unsigned g_S[NN * 64];
__device__ unsigned g_R[NN * 64];
__device__ unsigned g_agg[NN * 64];
__device__ unsigned g_hin[NN * 128];   // packed h_in (K=128 -> 64 pairs)
__device__ unsigned g_pin[NN * 16];    // packed p_in (K=16 -> 8 pairs)
__device__ unsigned g_w[54 * 8192];    // 54 weight slots, col-major packed, interleaved
__device__ float g_esum[NN * 16];
__device__ int   g_deg[NN];
__device__ int   g_rowptr[NN + 1];
__device__ int   g_cursor[NN];
__device__ int   g_col[EE];
__device__ int   g_eid[EE];
__device__ float g_Gh[LL * 16 * 64];
__device__ float g_ch[LL * 64];
__device__ float g_Gp[LL * 16 * 64];
__device__ float g_cp[LL * 64];

// ---------------- helpers ----------------
__device__ __forceinline__ float2 unpk(uint2 v) {
    __nv_bfloat162 h = *(__nv_bfloat162*)&v.x;
    __nv_bfloat162 l = *(__nv_bfloat162*)&v.y;
    return make_float2(__bfloat162float(h.x) + __bfloat162float(l.x),
                       __bfloat162float(h.y) + __bfloat162float(l.y));
}
__device__ __forceinline__ uint2 pk(float a, float b) {
    __nv_bfloat16 ha = __float2bfloat16_rn(a), hb = __float2bfloat16_rn(b);
    float la = a - __bfloat162float(ha), lb = b - __bfloat162float(hb);
    __nv_bfloat162 hw; hw.x = ha; hw.y = hb;
    __nv_bfloat162 lw; lw.x = __float2bfloat16_rn(la); lw.y = __float2bfloat16_rn(lb);
    uint2 r; r.x = *(unsigned*)&hw; r.y = *(unsigned*)&lw; return r;
}
__device__ __forceinline__ void mma_bf16(float* d, const unsigned* a, const unsigned* b) {
    asm volatile(
        "mma.sync.aligned.m16n8k16.row.col.f32.bf16.bf16.f32 "
        "{%0,%1,%2,%3}, {%4,%5,%6,%7}, {%8,%9}, {%0,%1,%2,%3};"
        : "+f"(d[0]), "+f"(d[1]), "+f"(d[2]), "+f"(d[3])
        : "r"(a[0]), "r"(a[1]), "r"(a[2]), "r"(a[3]), "r"(b[0]), "r"(b[1]));
}

// ---------------- setup kernels ----------------
__global__ void zero_kernel() {
    int i = blockIdx.x * blockDim.x + threadIdx.x;
    if (i < NN) g_deg[i] = 0;
}
__global__ void cursor_copy_kernel() {
    int i = blockIdx.x * blockDim.x + threadIdx.x;
    if (i < NN) g_cursor[i] = g_rowptr[i];
}
__global__ void out_kernel(float* __restrict__ out) {
    int i = blockIdx.x * blockDim.x + threadIdx.x;
    if (i >= NN * 32) return;
    int r = i >> 5, j = i & 31;
    float2 fh = unpk(*(const uint2*)&g_h[(size_t)r * 64 + j * 2]);
    float2 fpp = unpk(*(const uint2*)&g_p[(size_t)r * 64 + j * 2]);
    out[(size_t)r * 64 + 2 * j] = fh.x;
    out[(size_t)r * 64 + 2 * j + 1] = fh.y;
    out[(size_t)NN * 64 + (size_t)r * 64 + 2 * j] = fpp.x;
    out[(size_t)NN * 64 + (size_t)r * 64 + 2 * j + 1] = fpp.y;
}

// pack h_in / p_in into packed hi/lo
__global__ void pack_inputs(const float* __restrict__ h_in, const float* __restrict__ p_in) {
    int idx = blockIdx.x * blockDim.x + threadIdx.x;
    if (idx < NN * 64) {
        int r = idx >> 6, j = idx & 63;
        float v0 = h_in[(size_t)r * 128 + 2 * j];
        float v1 = h_in[(size_t)r * 128 + 2 * j + 1];
        *(uint2*)&g_hin[(size_t)idx * 2] = pk(v0, v1);
    } else if (idx < NN * 64 + NN * 8) {
        int k = idx - NN * 64;
        int r = k >> 3, j = k & 7;
        float v0 = p_in[(size_t)r * 16 + 2 * j];
        float v1 = p_in[(size_t)r * 16 + 2 * j + 1];
        *(uint2*)&g_pin[(size_t)k * 2] = pk(v0, v1);
    }
}

// pack all weight matrices: slot layout (col-major, interleaved hi/lo pairs)
// slot 0: he_W (K=128), slot 1: pe_W (K=16); per layer i, base b=2+i*13:
// +0 Wm_hs +1 Wm_ps +2 Wm_hr +3 Wm_pr +4 Wm_e +5 We_hs +6 We_hr +7 We_e
// +8 Wp_ps +9 Wp_pr +10 Wp_e +11 huW(K=128) +12 puW(K=128)
__global__ void pack_weights(const float* __restrict__ heW, const float* __restrict__ peW,
                             const float* __restrict__ hmW, const float* __restrict__ euW,
                             const float* __restrict__ pmW, const float* __restrict__ huW,
                             const float* __restrict__ puW) {
    int m = blockIdx.x;
    const float* src; int Kw;
    if (m == 0) { src = heW; Kw = 64; }
    else if (m == 1) { src = peW; Kw = 8; }
    else {
        int mm = m - 2, i = mm / 13, j = mm % 13;
        if (j < 5)       { src = hmW + (size_t)i * 20480 + j * 4096; Kw = 32; }
        else if (j < 8)  { src = euW + (size_t)i * 12288 + (j - 5) * 4096; Kw = 32; }
        else if (j < 10) { src = pmW + (size_t)i * 12288 + (j - 8) * 4096; Kw = 32; }
        else if (j == 10){ src = pmW + (size_t)i * 12288 + 2 * 4096; Kw = 32; }
        else if (j == 11){ src = huW + (size_t)i * 8192; Kw = 64; }
        else             { src = puW + (size_t)i * 8192; Kw = 64; }
    }
    unsigned* dst = g_w + (size_t)m * 8192;
    for (int idx = threadIdx.x; idx < 64 * Kw; idx += blockDim.x) {
        int c = idx & 63, k2 = idx >> 6;
        float v0 = src[(size_t)(2 * k2) * 64 + c];
        float v1 = src[(size_t)(2 * k2 + 1) * 64 + c];
        *(uint2*)&dst[(size_t)(c * Kw + k2) * 2] = pk(v0, v1);
    }
}

// ---------------- CSR build ----------------
__global__ void deg_kernel(const int* __restrict__ rec) {
    int j = blockIdx.x * blockDim.x + threadIdx.x;
    if (j < EE) atomicAdd(&g_deg[rec[j]], 1);
}
__global__ __launch_bounds__(1024) void scan_kernel(int n) {
    __shared__ int wsum[32];
    __shared__ int carry;
    int t = threadIdx.x, lane = t & 31, wid = t >> 5;
    if (t == 0) { carry = 0; g_rowptr[0] = 0; }
    __syncthreads();
    for (int base = 0; base < n; base += 1024) {
        int i = base + t;
        int v = (i < n) ? g_deg[i] : 0;
        int x = v;
        #pragma unroll
        for (int o = 1; o < 32; o <<= 1) {
            int y = __shfl_up_sync(0xffffffffu, x, o);
            if (lane >= o) x += y;
        }
        if (lane == 31) wsum[wid] = x;
        __syncthreads();
        if (wid == 0) {
            int s = wsum[lane];
            #pragma unroll
            for (int o = 1; o < 32; o <<= 1) {
                int y = __shfl_up_sync(0xffffffffu, s, o);
                if (lane >= o) s += y;
            }
            wsum[lane] = s;
        }
        __syncthreads();
        int off = carry + (wid ? wsum[wid - 1] : 0);
        if (i < n) g_rowptr[i + 1] = off + x;
        __syncthreads();
        if (t == 0) carry += wsum[31];
        __syncthreads();
    }
}
__global__ void fill_kernel(const int* __restrict__ send, const int* __restrict__ rec) {
    int j = blockIdx.x * blockDim.x + threadIdx.x;
    if (j < EE) {
        int pos = atomicAdd(&g_cursor[rec[j]], 1);
        g_col[pos] = send[j];
        g_eid[pos] = j;
    }
}
// esum[n][k] = sum of e_in over incoming edges (CSR, no atomics)
__global__ __launch_bounds__(256) void esum_csr(const float* __restrict__ e_in) {
    int t = threadIdx.x;
    int node = blockIdx.x * 8 + (t >> 5);
    if (node >= NN) return;
    int lane = t & 31;
    int beg = g_rowptr[node], end = g_rowptr[node + 1];
    float v = 0.f;
    for (int e = beg + (lane >> 4); e < end; e += 2)
        v += e_in[(size_t)g_eid[e] * 16 + (lane & 15)];
    v += __shfl_down_sync(0xffffffffu, v, 16);
    if (lane < 16) g_esum[node * 16 + lane] = v;
}

// ---------------- precompute per-layer small matrices ----------------
__global__ __launch_bounds__(1024) void precompute_small(
    const float* __restrict__ eeW, const float* __restrict__ eeb,
    const float* __restrict__ hmW, const float* __restrict__ hmb,
    const float* __restrict__ euW, const float* __restrict__ eub,
    const float* __restrict__ pmW, const float* __restrict__ pmb)
{
    __shared__ float sEW[1024], sec[64], sEW2[1024], sec2[64];
    int t = threadIdx.x;
    int r = t >> 6, c = t & 63;
    sEW[t] = eeW[t];
    if (t < 64) sec[t] = eeb[t];
    __syncthreads();
    for (int i = 0; i < LL; i++) {
        const float* Wm_e = hmW + (size_t)i * 320 * 64 + 256 * 64;
        const float* We_e = euW + (size_t)i * 192 * 64 + 128 * 64;
        const float* Wp_e = pmW + (size_t)i * 192 * 64 + 128 * 64;
        float s = 0.f;
        #pragma unroll 8
        for (int k = 0; k < 64; k++) s += sEW[r * 64 + k] * Wm_e[k * 64 + c];
        g_Gh[i * 1024 + t] = s;
        if (t < 64) {
            float s2 = hmb[i * 64 + t];
            for (int k = 0; k < 64; k++) s2 += sec[k] * Wm_e[k * 64 + t];
            g_ch[i * 64 + t] = s2;
        }
        s = 0.f;
        #pragma unroll 8
        for (int k = 0; k < 64; k++) s += sEW[r * 64 + k] * We_e[k * 64 + c];
        sEW2[t] = s;
        if (t < 64) {
            float s2 = eub[i * 64 + t];
            for (int k = 0; k < 64; k++) s2 += sec[k] * We_e[k * 64 + t];
            sec2[t] = s2;
        }
        __syncthreads();
        sEW[t] = sEW2[t];
        if (t < 64) sec[t] = sec2[t];
        __syncthreads();
        s = 0.f;
        #pragma unroll 8
        for (int k = 0; k < 64; k++) s += sEW[r * 64 + k] * Wp_e[k * 64 + c];
        g_Gp[i * 1024 + t] = s;
        if (t < 64) {
            float s2 = pmb[i * 64 + t];
            for (int k = 0; k < 64; k++) s2 += sec[k] * Wp_e[k * 64 + t];
            g_cp[i * 64 + t] = s2;
        }
        __syncthreads();
    }
}

// ---------------- dual-output tensor-core GEMM ----------------
// C1/C2 [N,64] packed = bias + sum_t A_t @ W{a,b}_t ; A/W packed bf16 hi/lo.
// 512 threads. Dual mode: 128-row tile, 4x(2x2) warps; single mode (C2=null):
// 256-row tile, 8x2 warps.
struct GemmArgs {
    const unsigned* A[4];
    const unsigned* Wa[4];
    const unsigned* Wb[4];
    int Aw[4];    // A pairs per row
    int Ws[4];    // W pairs per col
    int Kst[4];   // k-steps of 16
    int nterms;
    unsigned* C1; unsigned* C2;
    const float* b1; const float* b2;
};

__global__ __launch_bounds__(512) void dual_gemm(GemmArgs ga) {
    __shared__ unsigned sA_hi[256 * 12], sA_lo[256 * 12];
    __shared__ unsigned sWa_hi[64 * 12], sWa_lo[64 * 12];
    __shared__ unsigned sWb_hi[64 * 12], sWb_lo[64 * 12];

    int t = threadIdx.x;
    int w = t >> 5, lane = t & 31;
    int gq = lane >> 2, q = lane & 3;
    bool single = (ga.C2 == nullptr);
    int wm, wn, outsel, rows;
    if (single) { wm = w >> 1; wn = w & 1; outsel = 0; rows = 256; }
    else        { wm = w >> 2; outsel = (w >> 1) & 1; wn = w & 1; rows = 128; }
    int r0 = blockIdx.x * rows;

    float acc[2][4][4];
    #pragma unroll
    for (int mt = 0; mt < 2; mt++)
        #pragma unroll
        for (int nt = 0; nt < 4; nt++)
            #pragma unroll
            for (int i = 0; i < 4; i++) acc[mt][nt][i] = 0.f;

    for (int term = 0; term < 4; term++) {
        if (term >= ga.nterms) break;
        const unsigned* Ap = ga.A[term];
        int Aw = ga.Aw[term];
        int Kst = ga.Kst[term];
        int Wsv = ga.Ws[term];
        const unsigned* myWsrc = outsel ? ga.Wb[term] : ga.Wa[term];
        bool act = (myWsrc != nullptr);
        const unsigned* whp = outsel ? sWb_hi : sWa_hi;
        const unsigned* wlp = outsel ? sWb_lo : sWa_lo;

        for (int ks = 0; ks < Kst; ks++) {
            __syncthreads();
            // stage A (interleaved uint4 -> split hi/lo smem)
            {
                int reps = single ? 2 : 1;
                for (int rep = 0; rep < reps; rep++) {
                    int row = rep * 128 + (t >> 2);
                    int part = t & 3;
                    int gr = r0 + row;
                    uint4 v = make_uint4(0, 0, 0, 0);
                    if (gr < NN)
                        v = *(const uint4*)&Ap[(size_t)gr * 2 * Aw + ks * 16 + part * 4];
                    sA_hi[row * 12 + part * 2]     = v.x;
                    sA_lo[row * 12 + part * 2]     = v.y;
                    sA_hi[row * 12 + part * 2 + 1] = v.z;
                    sA_lo[row * 12 + part * 2 + 1] = v.w;
                }
            }
            // stage W: threads <256 stage Wa, >=256 stage Wb
            {
                int tt = t & 255;
                const unsigned* wp = (t < 256) ? ga.Wa[term] : ga.Wb[term];
                unsigned* dh = (t < 256) ? sWa_hi : sWb_hi;
                unsigned* dl = (t < 256) ? sWa_lo : sWb_lo;
                if (wp) {
                    int col = tt >> 2, part = tt & 3;
                    uint4 v = *(const uint4*)&wp[(size_t)col * 2 * Wsv + ks * 16 + part * 4];
                    dh[col * 12 + part * 2]     = v.x;
                    dl[col * 12 + part * 2]     = v.y;
                    dh[col * 12 + part * 2 + 1] = v.z;
                    dl[col * 12 + part * 2 + 1] = v.w;
                }
            }
            __syncthreads();
            if (!act) continue;

            unsigned ah[2][4], al[2][4];
            #pragma unroll
            for (int mt = 0; mt < 2; mt++) {
                int r = wm * 32 + mt * 16 + gq;
                ah[mt][0] = sA_hi[r * 12 + q];
                ah[mt][1] = sA_hi[(r + 8) * 12 + q];
                ah[mt][2] = sA_hi[r * 12 + q + 4];
                ah[mt][3] = sA_hi[(r + 8) * 12 + q + 4];
                al[mt][0] = sA_lo[r * 12 + q];
                al[mt][1] = sA_lo[(r + 8) * 12 + q];
                al[mt][2] = sA_lo[r * 12 + q + 4];
                al[mt][3] = sA_lo[(r + 8) * 12 + q + 4];
            }
            unsigned bh[4][2], bl[4][2];
            #pragma unroll
            for (int nt = 0; nt < 4; nt++) {
                int c = wn * 32 + nt * 8 + gq;
                bh[nt][0] = whp[c * 12 + q];
                bh[nt][1] = whp[c * 12 + q + 4];
                bl[nt][0] = wlp[c * 12 + q];
                bl[nt][1] = wlp[c * 12 + q + 4];
            }
            #pragma unroll
            for (int mt = 0; mt < 2; mt++)
                #pragma unroll
                for (int nt = 0; nt < 4; nt++) {
                    mma_bf16(acc[mt][nt], ah[mt], bh[nt]);
                    mma_bf16(acc[mt][nt], ah[mt], bl[nt]);
                    mma_bf16(acc[mt][nt], al[mt], bh[nt]);
                }
        }
    }

    unsigned* C = outsel ? ga.C2 : ga.C1;
    const float* bias = outsel ? ga.b2 : ga.b1;
    #pragma unroll
    for (int nt = 0; nt < 4; nt++) {
        int cb = wn * 32 + nt * 8 + q * 2;
        float bx = bias ? bias[cb] : 0.f;
        float by = bias ? bias[cb + 1] : 0.f;
        int wj = (cb >> 1) * 2;
        #pragma unroll
        for (int mt = 0; mt < 2; mt++) {
            int row = r0 + wm * 32 + mt * 16 + gq;
            if (row < NN)
                *(uint2*)&C[(size_t)row * 64 + wj] =
                    pk(acc[mt][nt][0] + bx, acc[mt][nt][1] + by);
            if (row + 8 < NN)
                *(uint2*)&C[(size_t)(row + 8) * 64 + wj] =
                    pk(acc[mt][nt][2] + bx, acc[mt][nt][3] + by);
        }
    }
}

// ---------------- SpMM: agg[n] = sum_{j:rec=n} S[send_j] + esum[n]@G + deg[n]*(R[n]+c) ----
__global__ __launch_bounds__(256) void spmm_kernel(
    unsigned* __restrict__ agg, const unsigned* __restrict__ S,
    const unsigned* __restrict__ R, int layer, int pbranch)
{
    __shared__ float sG[16 * 64];
    __shared__ float sc[64];
    int t = threadIdx.x;
    const float* G = (pbranch ? g_Gp : g_Gh) + layer * 1024;
    const float* cc = (pbranch ? g_cp : g_ch) + layer * 64;
    for (int i = t; i < 1024; i += 256) sG[i] = G[i];
    if (t < 64) sc[t] = cc[t];
    __syncthreads();
    int node = blockIdx.x * 8 + (t >> 5);
    if (node >= NN) return;
    int lane = t & 31;
    int beg = g_rowptr[node], end = g_rowptr[node + 1];
    float ax = 0.f, ay = 0.f;
    int e = beg;
    for (; e + 4 <= end; e += 4) {
        int u0 = g_col[e], u1 = g_col[e + 1], u2 = g_col[e + 2], u3 = g_col[e + 3];
        uint2 v0 = *(const uint2*)&S[(size_t)u0 * 64 + lane * 2];
        uint2 v1 = *(const uint2*)&S[(size_t)u1 * 64 + lane * 2];
        uint2 v2 = *(const uint2*)&S[(size_t)u2 * 64 + lane * 2];
        uint2 v3 = *(const uint2*)&S[(size_t)u3 * 64 + lane * 2];
        float2 f0 = unpk(v0), f1 = unpk(v1), f2 = unpk(v2), f3 = unpk(v3);
        ax += (f0.x + f1.x) + (f2.x + f3.x);
        ay += (f0.y + f1.y) + (f2.y + f3.y);
    }
    for (; e < end; e++) {
        int u = g_col[e];
        float2 f = unpk(*(const uint2*)&S[(size_t)u * 64 + lane * 2]);
        ax += f.x; ay += f.y;
    }
    float deg = (float)(end - beg);
    int c0 = lane * 2;
    float2 r2 = unpk(*(const uint2*)&R[(size_t)node * 64 + lane * 2]);
    float t0 = deg * (r2.x + sc[c0]) + ax;
    float t1 = deg * (r2.y + sc[c0 + 1]) + ay;
    #pragma unroll
    for (int k = 0; k < 16; k++) {
        float ev = g_esum[node * 16 + k];
        t0 += ev * sG[k * 64 + c0];
        t1 += ev * sG[k * 64 + c0 + 1];
    }
    *(uint2*)&agg[(size_t)node * 64 + lane * 2] = pk(t0, t1);
}

// ---------------- host ----------------
extern "C" void kernel_launch(void* const* d_in, const int* in_sizes, int n_in,
                              void* d_out, int out_size)
{
    const float* h_in = (const float*)d_in[0];
    const float* e_in = (const float*)d_in[1];
    const float* p_in = (const float*)d_in[2];
    const int*   ei   = (const int*)d_in[3];
    const int* send = ei;
    const int* rec  = ei + EE;
    const float* he_W = (const float*)d_in[4];
    const float* he_b = (const float*)d_in[5];
    const float* ee_W = (const float*)d_in[6];
    const float* ee_b = (const float*)d_in[7];
    const float* pe_W = (const float*)d_in[8];
    const float* pe_b = (const float*)d_in[9];
    const float* hm_W = (const float*)d_in[10];
    const float* hm_b = (const float*)d_in[11];
    const float* hu_W = (const float*)d_in[12];
    const float* hu_b = (const float*)d_in[13];
    const float* eu_W = (const float*)d_in[14];
    const float* eu_b = (const float*)d_in[15];
    const float* pm_W = (const float*)d_in[16];
    const float* pm_b = (const float*)d_in[17];
    const float* pu_W = (const float*)d_in[18];
    const float* pu_b = (const float*)d_in[19];

    static unsigned* fh = nullptr;
    static unsigned *fp, *fEA, *fEB, *fS, *fR, *fagg, *fhin, *fpin, *fw;
    if (fh == nullptr) {
        void* ptr;
        cudaGetSymbolAddress(&ptr, g_h);    fh   = (unsigned*)ptr;
        cudaGetSymbolAddress(&ptr, g_p);    fp   = (unsigned*)ptr;
        cudaGetSymbolAddress(&ptr, g_EA);   fEA  = (unsigned*)ptr;
        cudaGetSymbolAddress(&ptr, g_EB);   fEB  = (unsigned*)ptr;
        cudaGetSymbolAddress(&ptr, g_S);    fS   = (unsigned*)ptr;
        cudaGetSymbolAddress(&ptr, g_R);    fR   = (unsigned*)ptr;
        cudaGetSymbolAddress(&ptr, g_agg);  fagg = (unsigned*)ptr;
        cudaGetSymbolAddress(&ptr, g_hin);  fhin = (unsigned*)ptr;
        cudaGetSymbolAddress(&ptr, g_pin);  fpin = (unsigned*)ptr;
        cudaGetSymbolAddress(&ptr, g_w);    fw   = (unsigned*)ptr;
    }
    #define WSLOT(s) (fw + (size_t)(s) * 8192)

    const int EB256 = (EE + 255) / 256;
    const int GBD = (NN + 127) / 128;   // dual grid
    const int GBS = (NN + 255) / 256;   // single grid
    const int SB = (NN + 7) / 8;

    // ----- setup -----
    zero_kernel<<<(NN + 255) / 256, 256>>>();
    precompute_small<<<1, 1024>>>(ee_W, ee_b, hm_W, hm_b, eu_W, eu_b, pm_W, pm_b);
    pack_weights<<<54, 256>>>(he_W, pe_W, hm_W, eu_W, pm_W, hu_W, pu_W);
    pack_inputs<<<(NN * 72 + 255) / 256, 256>>>(h_in, p_in);

    deg_kernel<<<EB256, 256>>>(rec);
    scan_kernel<<<1, 1024>>>(NN);
    cursor_copy_kernel<<<(NN + 255) / 256, 256>>>();
    fill_kernel<<<EB256, 256>>>(send, rec);
    esum_csr<<<SB, 256>>>(e_in);

    GemmArgs ga;
    auto setT = [&](int idx, const unsigned* A, int Aw, int Kst,
                    const unsigned* Wa, const unsigned* Wb, int Ws) {
        ga.A[idx] = A; ga.Aw[idx] = Aw; ga.Kst[idx] = Kst;
        ga.Wa[idx] = Wa; ga.Wb[idx] = Wb; ga.Ws[idx] = Ws;
    };

    // ----- embeddings (single mode, 256-row tiles) -----
    ga = GemmArgs{};
    setT(0, fhin, 64, 8, WSLOT(0), nullptr, 64);
    ga.nterms = 1; ga.C1 = fh; ga.C2 = nullptr; ga.b1 = he_b; ga.b2 = nullptr;
    dual_gemm<<<GBS, 512>>>(ga);

    ga = GemmArgs{};
    setT(0, fpin, 8, 1, WSLOT(1), nullptr, 8);
    ga.nterms = 1; ga.C1 = fp; ga.C2 = nullptr; ga.b1 = pe_b; ga.b2 = nullptr;
    dual_gemm<<<GBS, 512>>>(ga);

    // ----- layers -----
    for (int i = 0; i < LL; i++) {
        int b = 2 + i * 13;

        // hSR: S = h@Wm_hs + p@Wm_ps + EA@Wm_e ; R = h@Wm_hr + p@Wm_pr + EB@Wm_e
        ga = GemmArgs{};
        setT(0, fh, 32, 4, WSLOT(b + 0), WSLOT(b + 2), 32);
        setT(1, fp, 32, 4, WSLOT(b + 1), WSLOT(b + 3), 32);
        ga.nterms = 2;
        if (i > 0) {
            setT(2, fEA, 32, 4, WSLOT(b + 4), nullptr, 32);
            setT(3, fEB, 32, 4, nullptr, WSLOT(b + 4), 32);
            ga.nterms = 4;
        }
        ga.C1 = fS; ga.C2 = fR; ga.b1 = nullptr; ga.b2 = nullptr;
        dual_gemm<<<GBD, 512>>>(ga);

        spmm_kernel<<<SB, 256>>>(fagg, fS, fR, i, 0);

        // h update: h = h@huW[0:64] + agg@huW[64:128] + hu_b
        ga = GemmArgs{};
        setT(0, fh,   32, 4, WSLOT(b + 11),      nullptr, 64);
        setT(1, fagg, 32, 4, WSLOT(b + 11) + 64, nullptr, 64);
        ga.nterms = 2; ga.C1 = fh; ga.C2 = nullptr;
        ga.b1 = hu_b + i * 64; ga.b2 = nullptr;
        dual_gemm<<<GBS, 512>>>(ga);

        // EAB: EA' = h@We_hs + EA@We_e ; EB' = h@We_hr + EB@We_e
        ga = GemmArgs{};
        setT(0, fh, 32, 4, WSLOT(b + 5), WSLOT(b + 6), 32);
        ga.nterms = 1;
        if (i > 0) {
            setT(1, fEA, 32, 4, WSLOT(b + 7), nullptr, 32);
            setT(2, fEB, 32, 4, nullptr, WSLOT(b + 7), 32);
            ga.nterms = 3;
        }
        ga.C1 = fEA; ga.C2 = fEB; ga.b1 = nullptr; ga.b2 = nullptr;
        dual_gemm<<<GBD, 512>>>(ga);

        // pSR: S = p@Wp_ps + EA'@Wp_e ; R = p@Wp_pr + EB'@Wp_e
        ga = GemmArgs{};
        setT(0, fp,  32, 4, WSLOT(b + 8),  WSLOT(b + 9), 32);
        setT(1, fEA, 32, 4, WSLOT(b + 10), nullptr, 32);
        setT(2, fEB, 32, 4, nullptr, WSLOT(b + 10), 32);
        ga.nterms = 3; ga.C1 = fS; ga.C2 = fR; ga.b1 = nullptr; ga.b2 = nullptr;
        dual_gemm<<<GBD, 512>>>(ga);

        spmm_kernel<<<SB, 256>>>(fagg, fS, fR, i, 1);

        // p update
        ga = GemmArgs{};
        setT(0, fp,   32, 4, WSLOT(b + 12),      nullptr, 64);
        setT(1, fagg, 32, 4, WSLOT(b + 12) + 64, nullptr, 64);
        ga.nterms = 2; ga.C1 = fp; ga.C2 = nullptr;
        ga.b1 = pu_b + i * 64; ga.b2 = nullptr;
        dual_gemm<<<GBS, 512>>>(ga);
    }

    // ----- output -----
    out_kernel<<<(NN * 32 + 255) / 256, 256>>>((float*)d_out);
}

// round 9
// speedup vs baseline: 1.1162x; 1.1162x over previous
#include <cuda_runtime.h>
#include <cuda_bf16.h>

#define NN 50000
#define NP 50048            // padded to 128-row multiple; pad rows stay zero
#define EE 800000
#define LL 4

// ---------------- packed bf16 hi/lo storage ----------------
// node array [NP][64] : word 2j = bf16x2 hi of cols (2j,2j+1), word 2j+1 = lo residuals.
__device__ unsigned g_h[NP * 64];
__device__ unsigned g_h2[NP * 64];
__device__ unsigned g_p[NP * 64];
__device__ unsigned g_p2[NP * 64];
__device__ unsigned g_EA[NP * 64];
__device__ unsigned g_EA2[NP * 64];
__device__ unsigned g_EB[NP * 64];
__device__ unsigned g_EB2[NP * 64];
__device__ unsigned g_S[NP * 64];
__device__ unsigned g_R[NP * 64];
__device__ unsigned g_agg[NP * 64];
__device__ unsigned g_hin[NP * 128];
__device__ unsigned g_pin[NP * 16];
__device__ unsigned g_w[54 * 8192];
__device__ float g_esum[NN * 16];
__device__ int   g_deg[NN];
__device__ int   g_rowptr[NN + 1];
__device__ int   g_cursor[NN];
__device__ int   g_col[EE];
__device__ int   g_eid[EE];
__device__ float g_Gh[LL * 16 * 64];
__device__ float g_ch[LL * 64];
__device__ float g_Gp[LL * 16 * 64];
__device__ float g_cp[LL * 64];

// ---------------- helpers ----------------
__device__ __forceinline__ float2 unpk(uint2 v) {
    __nv_bfloat162 h = *(__nv_bfloat162*)&v.x;
    __nv_bfloat162 l = *(__nv_bfloat162*)&v.y;
    return make_float2(__bfloat162float(h.x) + __bfloat162float(l.x),
                       __bfloat162float(h.y) + __bfloat162float(l.y));
}
__device__ __forceinline__ uint2 pk(float a, float b) {
    __nv_bfloat16 ha = __float2bfloat16_rn(a), hb = __float2bfloat16_rn(b);
    float la = a - __bfloat162float(ha), lb = b - __bfloat162float(hb);
    __nv_bfloat162 hw; hw.x = ha; hw.y = hb;
    __nv_bfloat162 lw; lw.x = __float2bfloat16_rn(la); lw.y = __float2bfloat16_rn(lb);
    uint2 r; r.x = *(unsigned*)&hw; r.y = *(unsigned*)&lw; return r;
}
__device__ __forceinline__ void mma_bf16(float* d, const unsigned* a, const unsigned* b) {
    asm volatile(
        "mma.sync.aligned.m16n8k16.row.col.f32.bf16.bf16.f32 "
        "{%0,%1,%2,%3}, {%4,%5,%6,%7}, {%8,%9}, {%0,%1,%2,%3};"
        : "+f"(d[0]), "+f"(d[1]), "+f"(d[2]), "+f"(d[3])
        : "r"(a[0]), "r"(a[1]), "r"(a[2]), "r"(a[3]), "r"(b[0]), "r"(b[1]));
}

// ---------------- setup kernels ----------------
__global__ void zero_kernel() {
    int i = blockIdx.x * blockDim.x + threadIdx.x;
    if (i < NN) g_deg[i] = 0;
}
__global__ void cursor_copy_kernel() {
    int i = blockIdx.x * blockDim.x + threadIdx.x;
    if (i < NN) g_cursor[i] = g_rowptr[i];
}
__global__ void out_kernel(float* __restrict__ out, const unsigned* __restrict__ hc,
                           const unsigned* __restrict__ pc) {
    int i = blockIdx.x * blockDim.x + threadIdx.x;
    if (i >= NN * 32) return;
    int r = i >> 5, j = i & 31;
    float2 fh = unpk(*(const uint2*)&hc[(size_t)r * 64 + j * 2]);
    float2 fpp = unpk(*(const uint2*)&pc[(size_t)r * 64 + j * 2]);
    out[(size_t)r * 64 + 2 * j] = fh.x;
    out[(size_t)r * 64 + 2 * j + 1] = fh.y;
    out[(size_t)NN * 64 + (size_t)r * 64 + 2 * j] = fpp.x;
    out[(size_t)NN * 64 + (size_t)r * 64 + 2 * j + 1] = fpp.y;
}

__global__ void pack_inputs(const float* __restrict__ h_in, const float* __restrict__ p_in) {
    int idx = blockIdx.x * blockDim.x + threadIdx.x;
    if (idx < NN * 64) {
        int r = idx >> 6, j = idx & 63;
        float v0 = h_in[(size_t)r * 128 + 2 * j];
        float v1 = h_in[(size_t)r * 128 + 2 * j + 1];
        *(uint2*)&g_hin[((size_t)r * 64 + j) * 2] = pk(v0, v1);
    } else if (idx < NN * 64 + NN * 8) {
        int k = idx - NN * 64;
        int r = k >> 3, j = k & 7;
        float v0 = p_in[(size_t)r * 16 + 2 * j];
        float v1 = p_in[(size_t)r * 16 + 2 * j + 1];
        *(uint2*)&g_pin[((size_t)r * 8 + j) * 2] = pk(v0, v1);
    }
}

// slot 0: he_W (64 pairs), slot 1: pe_W (8 pairs); per layer i, base b=2+i*13:
// +0 Wm_hs +1 Wm_ps +2 Wm_hr +3 Wm_pr +4 Wm_e +5 We_hs +6 We_hr +7 We_e
// +8 Wp_ps +9 Wp_pr +10 Wp_e +11 huW(64 pairs) +12 puW(64 pairs)
__global__ void pack_weights(const float* __restrict__ heW, const float* __restrict__ peW,
                             const float* __restrict__ hmW, const float* __restrict__ euW,
                             const float* __restrict__ pmW, const float* __restrict__ huW,
                             const float* __restrict__ puW) {
    int m = blockIdx.x;
    const float* src; int Kw;
    if (m == 0) { src = heW; Kw = 64; }
    else if (m == 1) { src = peW; Kw = 8; }
    else {
        int mm = m - 2, i = mm / 13, j = mm % 13;
        if (j < 5)       { src = hmW + (size_t)i * 20480 + j * 4096; Kw = 32; }
        else if (j < 8)  { src = euW + (size_t)i * 12288 + (j - 5) * 4096; Kw = 32; }
        else if (j < 10) { src = pmW + (size_t)i * 12288 + (j - 8) * 4096; Kw = 32; }
        else if (j == 10){ src = pmW + (size_t)i * 12288 + 2 * 4096; Kw = 32; }
        else if (j == 11){ src = huW + (size_t)i * 8192; Kw = 64; }
        else             { src = puW + (size_t)i * 8192; Kw = 64; }
    }
    unsigned* dst = g_w + (size_t)m * 8192;
    for (int idx = threadIdx.x; idx < 64 * Kw; idx += blockDim.x) {
        int c = idx & 63, k2 = idx >> 6;
        float v0 = src[(size_t)(2 * k2) * 64 + c];
        float v1 = src[(size_t)(2 * k2 + 1) * 64 + c];
        *(uint2*)&dst[(size_t)(c * Kw + k2) * 2] = pk(v0, v1);
    }
}

// ---------------- CSR build ----------------
__global__ void deg_kernel(const int* __restrict__ rec) {
    int j = blockIdx.x * blockDim.x + threadIdx.x;
    if (j < EE) atomicAdd(&g_deg[rec[j]], 1);
}
__global__ __launch_bounds__(1024) void scan_kernel(int n) {
    __shared__ int wsum[32];
    __shared__ int carry;
    int t = threadIdx.x, lane = t & 31, wid = t >> 5;
    if (t == 0) { carry = 0; g_rowptr[0] = 0; }
    __syncthreads();
    for (int base = 0; base < n; base += 1024) {
        int i = base + t;
        int v = (i < n) ? g_deg[i] : 0;
        int x = v;
        #pragma unroll
        for (int o = 1; o < 32; o <<= 1) {
            int y = __shfl_up_sync(0xffffffffu, x, o);
            if (lane >= o) x += y;
        }
        if (lane == 31) wsum[wid] = x;
        __syncthreads();
        if (wid == 0) {
            int s = wsum[lane];
            #pragma unroll
            for (int o = 1; o < 32; o <<= 1) {
                int y = __shfl_up_sync(0xffffffffu, s, o);
                if (lane >= o) s += y;
            }
            wsum[lane] = s;
        }
        __syncthreads();
        int off = carry + (wid ? wsum[wid - 1] : 0);
        if (i < n) g_rowptr[i + 1] = off + x;
        __syncthreads();
        if (t == 0) carry += wsum[31];
        __syncthreads();
    }
}
__global__ void fill_kernel(const int* __restrict__ send, const int* __restrict__ rec) {
    int j = blockIdx.x * blockDim.x + threadIdx.x;
    if (j < EE) {
        int pos = atomicAdd(&g_cursor[rec[j]], 1);
        g_col[pos] = send[j];
        g_eid[pos] = j;
    }
}
__global__ __launch_bounds__(256) void esum_csr(const float* __restrict__ e_in) {
    int t = threadIdx.x;
    int node = blockIdx.x * 8 + (t >> 5);
    if (node >= NN) return;
    int lane = t & 31;
    int beg = g_rowptr[node], end = g_rowptr[node + 1];
    float v = 0.f;
    for (int e = beg + (lane >> 4); e < end; e += 2)
        v += e_in[(size_t)g_eid[e] * 16 + (lane & 15)];
    v += __shfl_down_sync(0xffffffffu, v, 16);
    if (lane < 16) g_esum[node * 16 + lane] = v;
}

// ---------------- precompute per-layer small matrices ----------------
__global__ __launch_bounds__(1024) void precompute_small(
    const float* __restrict__ eeW, const float* __restrict__ eeb,
    const float* __restrict__ hmW, const float* __restrict__ hmb,
    const float* __restrict__ euW, const float* __restrict__ eub,
    const float* __restrict__ pmW, const float* __restrict__ pmb)
{
    __shared__ float sEW[1024], sec[64], sEW2[1024], sec2[64];
    int t = threadIdx.x;
    int r = t >> 6, c = t & 63;
    sEW[t] = eeW[t];
    if (t < 64) sec[t] = eeb[t];
    __syncthreads();
    for (int i = 0; i < LL; i++) {
        const float* Wm_e = hmW + (size_t)i * 320 * 64 + 256 * 64;
        const float* We_e = euW + (size_t)i * 192 * 64 + 128 * 64;
        const float* Wp_e = pmW + (size_t)i * 192 * 64 + 128 * 64;
        float s = 0.f;
        #pragma unroll 8
        for (int k = 0; k < 64; k++) s += sEW[r * 64 + k] * Wm_e[k * 64 + c];
        g_Gh[i * 1024 + t] = s;
        if (t < 64) {
            float s2 = hmb[i * 64 + t];
            for (int k = 0; k < 64; k++) s2 += sec[k] * Wm_e[k * 64 + t];
            g_ch[i * 64 + t] = s2;
        }
        s = 0.f;
        #pragma unroll 8
        for (int k = 0; k < 64; k++) s += sEW[r * 64 + k] * We_e[k * 64 + c];
        sEW2[t] = s;
        if (t < 64) {
            float s2 = eub[i * 64 + t];
            for (int k = 0; k < 64; k++) s2 += sec[k] * We_e[k * 64 + t];
            sec2[t] = s2;
        }
        __syncthreads();
        sEW[t] = sEW2[t];
        if (t < 64) sec[t] = sec2[t];
        __syncthreads();
        s = 0.f;
        #pragma unroll 8
        for (int k = 0; k < 64; k++) s += sEW[r * 64 + k] * Wp_e[k * 64 + c];
        g_Gp[i * 1024 + t] = s;
        if (t < 64) {
            float s2 = pmb[i * 64 + t];
            for (int k = 0; k < 64; k++) s2 += sec[k] * Wp_e[k * 64 + t];
            g_cp[i * 64 + t] = s2;
        }
        __syncthreads();
    }
}

// ---------------- streaming tensor-core GEMM ----------------
// grid (NP/128, ny). Block: 256 thr, 8 warps (wm 0..3, wn 0..1), 128-row tile.
// All weights staged to smem once (one sync); A fragments loaded directly from
// global as uint2 (hi,lo) — no syncs in mainloop, stores only in epilogue.
// blockIdx.y selects (Aa,Wa,C1,b1) vs (Ab,Wb,C2,b2).
struct GArgs {
    const unsigned* Aa[3]; const unsigned* Ab[3];
    const unsigned* Wa[3]; const unsigned* Wb[3];
    int Aw2[3];     // A row stride in u32 words
    int Wst[3];     // W slot column stride in pairs
    int Kst[3];     // k-steps of 16
    int nterms;
    unsigned* C1; unsigned* C2;
    const float* b1; const float* b2;
};

__global__ __launch_bounds__(256) void stream_gemm(GArgs ga) {
    extern __shared__ unsigned sW[];
    int y = blockIdx.y;
    int t = threadIdx.x;
    int w = t >> 5, lane = t & 31;
    int wm = w >> 1, wn = w & 1;
    int gq = lane >> 2, q = lane & 3;

    // ---- stage all weights (cs = pairs*2 + 2 pad words per column) ----
    int off = 0;
    for (int tm = 0; tm < ga.nterms; tm++) {
        const unsigned* Wg = y ? ga.Wb[tm] : ga.Wa[tm];
        int Tp = ga.Kst[tm] * 8;
        int cs = Tp * 2 + 2;
        int wst = ga.Wst[tm];
        for (int idx = t; idx < 64 * Tp; idx += 256) {
            int c = idx / Tp, p = idx - c * Tp;
            uint2 v = *(const uint2*)&Wg[(size_t)(c * wst + p) * 2];
            sW[off + c * cs + p * 2] = v.x;
            sW[off + c * cs + p * 2 + 1] = v.y;
        }
        off += 64 * cs;
    }
    __syncthreads();

    float acc[2][4][4];
    #pragma unroll
    for (int mt = 0; mt < 2; mt++)
        #pragma unroll
        for (int nt = 0; nt < 4; nt++)
            #pragma unroll
            for (int i = 0; i < 4; i++) acc[mt][nt][i] = 0.f;

    int rowb = blockIdx.x * 128 + wm * 32 + gq;

    off = 0;
    for (int tm = 0; tm < ga.nterms; tm++) {
        const unsigned* A = y ? ga.Ab[tm] : ga.Aa[tm];
        int aw2 = ga.Aw2[tm];
        int kst = ga.Kst[tm];
        int cs = kst * 16 + 2;
        const unsigned* wsm = sW + off;
        for (int ks = 0; ks < kst; ks++) {
            unsigned ah[2][4], al[2][4];
            #pragma unroll
            for (int mt = 0; mt < 2; mt++) {
                size_t rb0 = (size_t)(rowb + mt * 16) * aw2;
                size_t rb8 = (size_t)(rowb + mt * 16 + 8) * aw2;
                int p0 = (ks * 8 + q) * 2, p1 = (ks * 8 + q + 4) * 2;
                uint2 v0 = *(const uint2*)&A[rb0 + p0];
                uint2 v1 = *(const uint2*)&A[rb8 + p0];
                uint2 v2 = *(const uint2*)&A[rb0 + p1];
                uint2 v3 = *(const uint2*)&A[rb8 + p1];
                ah[mt][0] = v0.x; al[mt][0] = v0.y;
                ah[mt][1] = v1.x; al[mt][1] = v1.y;
                ah[mt][2] = v2.x; al[mt][2] = v2.y;
                ah[mt][3] = v3.x; al[mt][3] = v3.y;
            }
            #pragma unroll
            for (int nt = 0; nt < 4; nt++) {
                int c = wn * 32 + nt * 8 + gq;
                uint2 b0 = *(const uint2*)&wsm[c * cs + (ks * 8 + q) * 2];
                uint2 b1 = *(const uint2*)&wsm[c * cs + (ks * 8 + q + 4) * 2];
                unsigned bh[2] = {b0.x, b1.x};
                unsigned bl[2] = {b0.y, b1.y};
                #pragma unroll
                for (int mt = 0; mt < 2; mt++) {
                    mma_bf16(acc[mt][nt], ah[mt], bh);
                    mma_bf16(acc[mt][nt], ah[mt], bl);
                    mma_bf16(acc[mt][nt], al[mt], bh);
                }
            }
        }
        off += 64 * cs;
    }

    // ---- epilogue ----
    unsigned* C = y ? ga.C2 : ga.C1;
    const float* bias = y ? ga.b2 : ga.b1;
    #pragma unroll
    for (int nt = 0; nt < 4; nt++) {
        int cb = wn * 32 + nt * 8 + q * 2;
        float bx = bias ? bias[cb] : 0.f;
        float by = bias ? bias[cb + 1] : 0.f;
        #pragma unroll
        for (int mt = 0; mt < 2; mt++) {
            int row = blockIdx.x * 128 + wm * 32 + mt * 16 + gq;
            if (row < NN)
                *(uint2*)&C[(size_t)row * 64 + cb] =
                    pk(acc[mt][nt][0] + bx, acc[mt][nt][1] + by);
            if (row + 8 < NN)
                *(uint2*)&C[(size_t)(row + 8) * 64 + cb] =
                    pk(acc[mt][nt][2] + bx, acc[mt][nt][3] + by);
        }
    }
}

// ---------------- SpMM: agg[n] = sum_{j:rec=n} S[send_j] + esum[n]@G + deg[n]*(R[n]+c) ----
__global__ __launch_bounds__(256) void spmm_kernel(
    unsigned* __restrict__ agg, const unsigned* __restrict__ S,
    const unsigned* __restrict__ R, int layer, int pbranch)
{
    __shared__ float sG[16 * 64];
    __shared__ float sc[64];
    int t = threadIdx.x;
    const float* G = (pbranch ? g_Gp : g_Gh) + layer * 1024;
    const float* cc = (pbranch ? g_cp : g_ch) + layer * 64;
    for (int i = t; i < 1024; i += 256) sG[i] = G[i];
    if (t < 64) sc[t] = cc[t];
    __syncthreads();
    int node = blockIdx.x * 8 + (t >> 5);
    if (node >= NN) return;
    int lane = t & 31;
    int beg = g_rowptr[node], end = g_rowptr[node + 1];
    float ax = 0.f, ay = 0.f;
    int e = beg;
    for (; e + 4 <= end; e += 4) {
        int u0 = g_col[e], u1 = g_col[e + 1], u2 = g_col[e + 2], u3 = g_col[e + 3];
        uint2 v0 = *(const uint2*)&S[(size_t)u0 * 64 + lane * 2];
        uint2 v1 = *(const uint2*)&S[(size_t)u1 * 64 + lane * 2];
        uint2 v2 = *(const uint2*)&S[(size_t)u2 * 64 + lane * 2];
        uint2 v3 = *(const uint2*)&S[(size_t)u3 * 64 + lane * 2];
        float2 f0 = unpk(v0), f1 = unpk(v1), f2 = unpk(v2), f3 = unpk(v3);
        ax += (f0.x + f1.x) + (f2.x + f3.x);
        ay += (f0.y + f1.y) + (f2.y + f3.y);
    }
    for (; e < end; e++) {
        int u = g_col[e];
        float2 f = unpk(*(const uint2*)&S[(size_t)u * 64 + lane * 2]);
        ax += f.x; ay += f.y;
    }
    float deg = (float)(end - beg);
    int c0 = lane * 2;
    float2 r2 = unpk(*(const uint2*)&R[(size_t)node * 64 + lane * 2]);
    float t0 = deg * (r2.x + sc[c0]) + ax;
    float t1 = deg * (r2.y + sc[c0 + 1]) + ay;
    #pragma unroll
    for (int k = 0; k < 16; k++) {
        float ev = g_esum[node * 16 + k];
        t0 += ev * sG[k * 64 + c0];
        t1 += ev * sG[k * 64 + c0 + 1];
    }
    *(uint2*)&agg[(size_t)node * 64 + lane * 2] = pk(t0, t1);
}

// ---------------- host ----------------
extern "C" void kernel_launch(void* const* d_in, const int* in_sizes, int n_in,
                              void* d_out, int out_size)
{
    const float* h_in = (const float*)d_in[0];
    const float* e_in = (const float*)d_in[1];
    const float* p_in = (const float*)d_in[2];
    const int*   ei   = (const int*)d_in[3];
    const int* send = ei;
    const int* rec  = ei + EE;
    const float* he_W = (const float*)d_in[4];
    const float* he_b = (const float*)d_in[5];
    const float* ee_W = (const float*)d_in[6];
    const float* ee_b = (const float*)d_in[7];
    const float* pe_W = (const float*)d_in[8];
    const float* pe_b = (const float*)d_in[9];
    const float* hm_W = (const float*)d_in[10];
    const float* hm_b = (const float*)d_in[11];
    const float* hu_W = (const float*)d_in[12];
    const float* hu_b = (const float*)d_in[13];
    const float* eu_W = (const float*)d_in[14];
    const float* eu_b = (const float*)d_in[15];
    const float* pm_W = (const float*)d_in[16];
    const float* pm_b = (const float*)d_in[17];
    const float* pu_W = (const float*)d_in[18];
    const float* pu_b = (const float*)d_in[19];

    static unsigned* base_h = nullptr;
    static unsigned *base_h2, *base_p, *base_p2, *base_EA, *base_EA2,
                    *base_EB, *base_EB2, *fS, *fR, *fagg, *fhin, *fpin, *fw;
    if (base_h == nullptr) {
        void* ptr;
        cudaGetSymbolAddress(&ptr, g_h);    base_h   = (unsigned*)ptr;
        cudaGetSymbolAddress(&ptr, g_h2);   base_h2  = (unsigned*)ptr;
        cudaGetSymbolAddress(&ptr, g_p);    base_p   = (unsigned*)ptr;
        cudaGetSymbolAddress(&ptr, g_p2);   base_p2  = (unsigned*)ptr;
        cudaGetSymbolAddress(&ptr, g_EA);   base_EA  = (unsigned*)ptr;
        cudaGetSymbolAddress(&ptr, g_EA2);  base_EA2 = (unsigned*)ptr;
        cudaGetSymbolAddress(&ptr, g_EB);   base_EB  = (unsigned*)ptr;
        cudaGetSymbolAddress(&ptr, g_EB2);  base_EB2 = (unsigned*)ptr;
        cudaGetSymbolAddress(&ptr, g_S);    fS   = (unsigned*)ptr;
        cudaGetSymbolAddress(&ptr, g_R);    fR   = (unsigned*)ptr;
        cudaGetSymbolAddress(&ptr, g_agg);  fagg = (unsigned*)ptr;
        cudaGetSymbolAddress(&ptr, g_hin);  fhin = (unsigned*)ptr;
        cudaGetSymbolAddress(&ptr, g_pin);  fpin = (unsigned*)ptr;
        cudaGetSymbolAddress(&ptr, g_w);    fw   = (unsigned*)ptr;
        cudaFuncSetAttribute(stream_gemm,
                             cudaFuncAttributeMaxDynamicSharedMemorySize, 56 * 1024);
    }
    #define WSLOT(s) (fw + (size_t)(s) * 8192)

    // ping-pong cursors (fixed sequence every call -> deterministic)
    unsigned *hc = base_h, *hn = base_h2;
    unsigned *pc = base_p, *pn = base_p2;
    unsigned *EAc = base_EA, *EAn = base_EA2;
    unsigned *EBc = base_EB, *EBn = base_EB2;

    const int EB256 = (EE + 255) / 256;
    const int GB = NP / 128;   // 391
    const int SB = (NN + 7) / 8;

    // ----- setup -----
    zero_kernel<<<(NN + 255) / 256, 256>>>();
    precompute_small<<<1, 1024>>>(ee_W, ee_b, hm_W, hm_b, eu_W, eu_b, pm_W, pm_b);
    pack_weights<<<54, 256>>>(he_W, pe_W, hm_W, eu_W, pm_W, hu_W, pu_W);
    pack_inputs<<<(NN * 72 + 255) / 256, 256>>>(h_in, p_in);

    deg_kernel<<<EB256, 256>>>(rec);
    scan_kernel<<<1, 1024>>>(NN);
    cursor_copy_kernel<<<(NN + 255) / 256, 256>>>();
    fill_kernel<<<EB256, 256>>>(send, rec);
    esum_csr<<<SB, 256>>>(e_in);

    GArgs ga;
    auto setT = [&](int idx, const unsigned* Aa, const unsigned* Ab, int Aw2, int Kst,
                    const unsigned* Wa, const unsigned* Wb, int Wst) {
        ga.Aa[idx] = Aa; ga.Ab[idx] = Ab; ga.Aw2[idx] = Aw2; ga.Kst[idx] = Kst;
        ga.Wa[idx] = Wa; ga.Wb[idx] = Wb; ga.Wst[idx] = Wst;
    };
    auto smemBytes = [&]() {
        int s = 0;
        for (int tmi = 0; tmi < ga.nterms; tmi++) s += 64 * (ga.Kst[tmi] * 16 + 2);
        return (size_t)s * 4;
    };

    // ----- embeddings -----
    ga = GArgs{};
    setT(0, fhin, fhin, 128, 8, WSLOT(0), WSLOT(0), 64);
    ga.nterms = 1; ga.C1 = hc; ga.C2 = nullptr; ga.b1 = he_b; ga.b2 = nullptr;
    stream_gemm<<<dim3(GB, 1), 256, smemBytes()>>>(ga);

    ga = GArgs{};
    setT(0, fpin, fpin, 16, 1, WSLOT(1), WSLOT(1), 8);
    ga.nterms = 1; ga.C1 = pc; ga.C2 = nullptr; ga.b1 = pe_b; ga.b2 = nullptr;
    stream_gemm<<<dim3(GB, 1), 256, smemBytes()>>>(ga);

    // ----- layers -----
    for (int i = 0; i < LL; i++) {
        int b = 2 + i * 13;

        // hSR (dual): S = h@Wm_hs + p@Wm_ps + EA@Wm_e ; R = h@Wm_hr + p@Wm_pr + EB@Wm_e
        ga = GArgs{};
        setT(0, hc, hc, 64, 4, WSLOT(b + 0), WSLOT(b + 2), 32);
        setT(1, pc, pc, 64, 4, WSLOT(b + 1), WSLOT(b + 3), 32);
        ga.nterms = 2;
        if (i > 0) {
            setT(2, EAc, EBc, 64, 4, WSLOT(b + 4), WSLOT(b + 4), 32);
            ga.nterms = 3;
        }
        ga.C1 = fS; ga.C2 = fR; ga.b1 = nullptr; ga.b2 = nullptr;
        stream_gemm<<<dim3(GB, 2), 256, smemBytes()>>>(ga);

        spmm_kernel<<<SB, 256>>>(fagg, fS, fR, i, 0);

        // h update -> hn (no in-place)
        ga = GArgs{};
        setT(0, hc,   hc,   64, 4, WSLOT(b + 11),      WSLOT(b + 11),      64);
        setT(1, fagg, fagg, 64, 4, WSLOT(b + 11) + 64, WSLOT(b + 11) + 64, 64);
        ga.nterms = 2; ga.C1 = hn; ga.C2 = nullptr;
        ga.b1 = hu_b + i * 64; ga.b2 = nullptr;
        stream_gemm<<<dim3(GB, 1), 256, smemBytes()>>>(ga);
        { unsigned* tmp = hc; hc = hn; hn = tmp; }

        // EAB (dual): EA' = h@We_hs + EA@We_e ; EB' = h@We_hr + EB@We_e  -> EAn/EBn
        ga = GArgs{};
        setT(0, hc, hc, 64, 4, WSLOT(b + 5), WSLOT(b + 6), 32);
        ga.nterms = 1;
        if (i > 0) {
            setT(1, EAc, EBc, 64, 4, WSLOT(b + 7), WSLOT(b + 7), 32);
            ga.nterms = 2;
        }
        ga.C1 = EAn; ga.C2 = EBn; ga.b1 = nullptr; ga.b2 = nullptr;
        stream_gemm<<<dim3(GB, 2), 256, smemBytes()>>>(ga);
        { unsigned* tmp = EAc; EAc = EAn; EAn = tmp; }
        { unsigned* tmp = EBc; EBc = EBn; EBn = tmp; }

        // pSR (dual): S = p@Wp_ps + EA@Wp_e ; R = p@Wp_pr + EB@Wp_e
        ga = GArgs{};
        setT(0, pc, pc, 64, 4, WSLOT(b + 8), WSLOT(b + 9), 32);
        setT(1, EAc, EBc, 64, 4, WSLOT(b + 10), WSLOT(b + 10), 32);
        ga.nterms = 2; ga.C1 = fS; ga.C2 = fR; ga.b1 = nullptr; ga.b2 = nullptr;
        stream_gemm<<<dim3(GB, 2), 256, smemBytes()>>>(ga);

        spmm_kernel<<<SB, 256>>>(fagg, fS, fR, i, 1);

        // p update -> pn
        ga = GArgs{};
        setT(0, pc,   pc,   64, 4, WSLOT(b + 12),      WSLOT(b + 12),      64);
        setT(1, fagg, fagg, 64, 4, WSLOT(b + 12) + 64, WSLOT(b + 12) + 64, 64);
        ga.nterms = 2; ga.C1 = pn; ga.C2 = nullptr;
        ga.b1 = pu_b + i * 64; ga.b2 = nullptr;
        stream_gemm<<<dim3(GB, 1), 256, smemBytes()>>>(ga);
        { unsigned* tmp = pc; pc = pn; pn = tmp; }
    }

    // ----- output -----
    out_kernel<<<(NN * 32 + 255) / 256, 256>>>((float*)d_out, hc, pc);
}